// round 5
// baseline (speedup 1.0000x reference)
#include <cuda_runtime.h>

#define NEGV (-1e30f)

__device__ __forceinline__ float4 fmax4(float4 a, float4 b) {
    a.x = fmaxf(a.x, b.x);
    a.y = fmaxf(a.y, b.y);
    a.z = fmaxf(a.z, b.z);
    a.w = fmaxf(a.w, b.w);
    return a;
}

// One warp per (token, side); each warp covers the full D=256 row with two
// coalesced LDG.128 (lane and lane+32 float4 columns). Block = 128 threads
// = 4 warps = 2 tokens x 2 sides.
// Lane p holds paths[token][p] (P == 32), broadcast with shfl that depends
// only on register state -> unrolled iterations keep 8 loads in flight.
__global__ __launch_bounds__(128) void path_max_kernel(
    const float* __restrict__ inputs,   // [B,L,D] f32, D=256
    const int*   __restrict__ lpaths,   // [B,L,P]
    const int*   __restrict__ rpaths,   // [B,L,P]
    const int*   __restrict__ llens,    // [B,L]
    const int*   __restrict__ rlens,    // [B,L]
    const int*   __restrict__ slens,    // [B]
    float*       __restrict__ out)      // [B,L,2D]
{
    constexpr int L = 512, P = 32;

    const int warp  = threadIdx.x >> 5;
    const int lane  = threadIdx.x & 31;
    const int token = blockIdx.x * 2 + (warp >> 1);
    const int side  = warp & 1;          // 0 = left, 1 = right
    const int b     = token >> 9;        // token / L
    const int l     = token & (L - 1);   // token % L

    // Output: token row has 512 floats = 128 float4; this warp owns the
    // [side*64, side*64+64) float4 range, split as lane / lane+32.
    float4* o4 = reinterpret_cast<float4*>(out)
               + (size_t)token * 128 + side * 64 + lane;

    if (l >= __ldg(&slens[b])) {
        const float4 z = make_float4(0.f, 0.f, 0.f, 0.f);
        o4[0]  = z;
        o4[32] = z;
        return;
    }

    const int* __restrict__ paths = side ? rpaths : lpaths;
    const int len = side ? __ldg(&rlens[token]) : __ldg(&llens[token]);
    const int my  = __ldg(&paths[(size_t)token * P + lane]);

    // Row of inputs[b] is 64 float4; warp reads float4 columns lane, lane+32.
    const float4* __restrict__ base =
        reinterpret_cast<const float4*>(inputs)
        + (size_t)b * L * 64 + lane;

    float4 m0 = make_float4(NEGV, NEGV, NEGV, NEGV);
    float4 m1 = m0;

    int idx = __shfl_sync(0xffffffffu, my, 0);
    #pragma unroll 4
    for (int p = 0; p < len; ++p) {
        const float4* row = base + (size_t)idx * 64;
        const float4 v0 = __ldg(row);
        const float4 v1 = __ldg(row + 32);
        idx = __shfl_sync(0xffffffffu, my, (p + 1) & 31);  // independent of v
        m0 = fmax4(m0, v0);
        m1 = fmax4(m1, v1);
    }

    o4[0]  = m0;
    o4[32] = m1;
}

extern "C" void kernel_launch(void* const* d_in, const int* in_sizes, int n_in,
                              void* d_out, int out_size) {
    const float* inputs = (const float*)d_in[0];
    const int*   lpaths = (const int*)d_in[1];
    const int*   rpaths = (const int*)d_in[2];
    const int*   llens  = (const int*)d_in[3];
    const int*   rlens  = (const int*)d_in[4];
    const int*   slens  = (const int*)d_in[5];

    const int B = in_sizes[5];      // sent_lens has B elements
    const int tokens = B * 512;
    const int blocks = tokens / 2;  // 2 tokens per 128-thread block

    path_max_kernel<<<blocks, 128>>>(inputs, lpaths, rpaths,
                                     llens, rlens, slens,
                                     (float*)d_out);
}

// round 6
// speedup vs baseline: 1.0021x; 1.0021x over previous
#include <cuda_runtime.h>

#define NEGV (-1e30f)

__device__ __forceinline__ float4 fmax4(float4 a, float4 b) {
    a.x = fmaxf(a.x, b.x);
    a.y = fmaxf(a.y, b.y);
    a.z = fmaxf(a.z, b.z);
    a.w = fmaxf(a.w, b.w);
    return a;
}

// One warp per (token, side); each warp covers the full D=256 row with two
// coalesced LDG.128 (lane and lane+32 float4 columns). Block = 128 threads
// = 4 warps = 2 tokens x 2 sides.
// Lane p holds paths[token][p] (P == 32), broadcast with shfl that depends
// only on register state -> unrolled iterations keep 8 loads in flight.
__global__ __launch_bounds__(128) void path_max_kernel(
    const float* __restrict__ inputs,   // [B,L,D] f32, D=256
    const int*   __restrict__ lpaths,   // [B,L,P]
    const int*   __restrict__ rpaths,   // [B,L,P]
    const int*   __restrict__ llens,    // [B,L]
    const int*   __restrict__ rlens,    // [B,L]
    const int*   __restrict__ slens,    // [B]
    float*       __restrict__ out)      // [B,L,2D]
{
    constexpr int L = 512, P = 32;

    const int warp  = threadIdx.x >> 5;
    const int lane  = threadIdx.x & 31;
    const int token = blockIdx.x * 2 + (warp >> 1);
    const int side  = warp & 1;          // 0 = left, 1 = right
    const int b     = token >> 9;        // token / L
    const int l     = token & (L - 1);   // token % L

    // Output: token row has 512 floats = 128 float4; this warp owns the
    // [side*64, side*64+64) float4 range, split as lane / lane+32.
    float4* o4 = reinterpret_cast<float4*>(out)
               + (size_t)token * 128 + side * 64 + lane;

    if (l >= __ldg(&slens[b])) {
        const float4 z = make_float4(0.f, 0.f, 0.f, 0.f);
        o4[0]  = z;
        o4[32] = z;
        return;
    }

    const int* __restrict__ paths = side ? rpaths : lpaths;
    const int len = side ? __ldg(&rlens[token]) : __ldg(&llens[token]);
    const int my  = __ldg(&paths[(size_t)token * P + lane]);

    // Row of inputs[b] is 64 float4; warp reads float4 columns lane, lane+32.
    const float4* __restrict__ base =
        reinterpret_cast<const float4*>(inputs)
        + (size_t)b * L * 64 + lane;

    float4 m0 = make_float4(NEGV, NEGV, NEGV, NEGV);
    float4 m1 = m0;

    int idx = __shfl_sync(0xffffffffu, my, 0);
    #pragma unroll 4
    for (int p = 0; p < len; ++p) {
        const float4* row = base + (size_t)idx * 64;
        const float4 v0 = __ldg(row);
        const float4 v1 = __ldg(row + 32);
        idx = __shfl_sync(0xffffffffu, my, (p + 1) & 31);  // independent of v
        m0 = fmax4(m0, v0);
        m1 = fmax4(m1, v1);
    }

    o4[0]  = m0;
    o4[32] = m1;
}

extern "C" void kernel_launch(void* const* d_in, const int* in_sizes, int n_in,
                              void* d_out, int out_size) {
    const float* inputs = (const float*)d_in[0];
    const int*   lpaths = (const int*)d_in[1];
    const int*   rpaths = (const int*)d_in[2];
    const int*   llens  = (const int*)d_in[3];
    const int*   rlens  = (const int*)d_in[4];
    const int*   slens  = (const int*)d_in[5];

    const int B = in_sizes[5];      // sent_lens has B elements
    const int tokens = B * 512;
    const int blocks = tokens / 2;  // 2 tokens per 128-thread block

    path_max_kernel<<<blocks, 128>>>(inputs, lpaths, rpaths,
                                     llens, rlens, slens,
                                     (float*)d_out);
}